// round 1
// baseline (speedup 1.0000x reference)
#include <cuda_runtime.h>
#include <cuda_bf16.h>

// ShiftLayer: out[b,t,c] = in[b, t + off[c], c], off = {0,-1,+1} by c%3,
// zero padding at sequence ends. B=8, L=8192, C=384, fp32.
//
// Strategy: smem row-tile per block. Block = (b, 32-row chunk).
// Stage rows [t0-1, t0+R] (R+2 = 34 rows, 51 KB) with coalesced float4 loads,
// then gather per-channel shifted values from smem and write coalesced float4.
// DRAM traffic ~= 1.06x read + 1.0x write of the 100.7 MB tensor.

#define B_DIM 8
#define L_DIM 8192
#define C_DIM 384
#define R_ROWS 32
#define THREADS 256

__global__ __launch_bounds__(THREADS)
void ShiftLayer_66932770341347_kernel(const float* __restrict__ in,
                                      float* __restrict__ out) {
    __shared__ float tile[(R_ROWS + 2) * C_DIM];

    const int chunks_per_b = L_DIM / R_ROWS;        // 256
    const int blk = blockIdx.x;
    const int b  = blk / chunks_per_b;
    const int t0 = (blk % chunks_per_b) * R_ROWS;

    const float* base = in + (size_t)b * L_DIM * C_DIM;
    const int tid = threadIdx.x;

    // ---- Stage rows t0-1 .. t0+R into smem (zero-fill halo out of range) ----
    const int CV = C_DIM / 4;                        // 96 float4 per row
    const int NV = (R_ROWS + 2) * CV;                // 34*96 = 3264 float4
    #pragma unroll 4
    for (int i = tid; i < NV; i += THREADS) {
        int r  = i / CV;                             // 0..33  (tile row)
        int cc = (i - r * CV) * 4;                   // channel base
        int gr = t0 - 1 + r;                         // global sequence row
        float4 v = make_float4(0.f, 0.f, 0.f, 0.f);
        if (gr >= 0 && gr < L_DIM)
            v = *reinterpret_cast<const float4*>(base + (size_t)gr * C_DIM + cc);
        *reinterpret_cast<float4*>(&tile[r * C_DIM + cc]) = v;
    }
    __syncthreads();

    // ---- Gather shifted channels and write coalesced float4 ----
    float* obase = out + (size_t)b * L_DIM * C_DIM + (size_t)t0 * C_DIM;
    const int NO = R_ROWS * CV;                      // 32*96 = 3072 float4
    #pragma unroll 4
    for (int i = tid; i < NO; i += THREADS) {
        int r  = i / CV;                             // 0..R-1 (output row in chunk)
        int cc = (i - r * CV) * 4;                   // channel base
        const float* srow = &tile[(r + 1) * C_DIM];  // row index r+1 = global row t0+r
        float4 v;
        #pragma unroll
        for (int j = 0; j < 4; ++j) {
            int c = cc + j;
            int m = c % 3;                           // const-div, magic-mul in SASS
            int off = (m == 1) ? -1 : ((m == 2) ? 1 : 0);
            reinterpret_cast<float*>(&v)[j] = srow[off * C_DIM + c];
        }
        *reinterpret_cast<float4*>(obase + (size_t)r * C_DIM + cc) = v;
    }
}

extern "C" void kernel_launch(void* const* d_in, const int* in_sizes, int n_in,
                              void* d_out, int out_size) {
    const float* mem = (const float*)d_in[0];
    float* out = (float*)d_out;
    (void)in_sizes; (void)n_in; (void)out_size;

    const int grid = B_DIM * (L_DIM / R_ROWS);       // 8 * 256 = 2048 blocks
    ShiftLayer_66932770341347_kernel<<<grid, THREADS>>>(mem, out);
}

// round 2
// speedup vs baseline: 1.3258x; 1.3258x over previous
#include <cuda_runtime.h>
#include <cuda_bf16.h>

// ShiftLayer: out[b,t,c] = in[b, t+off[c], c], off[c] = {0,-1,+1} for c%3 = {0,1,2},
// zero padding at sequence ends. B=8, L=8192, C=384, fp32.
//
// Strategy: warp-per-(b, 16-row chunk). Lane i owns channels {4i, 4i+128, 4i+256}
// (three float4s). All global loads/stores are perfectly coalesced (512B/warp op).
// Rows stream through registers (prev/cur/next rotation) — each input row loaded
// once, no shared memory, no syncs. Per-lane channel residues are loop-invariant,
// so the 3-way source routing is just loop-invariant predicated selects.

#define B_DIM 8
#define L_DIM 8192
#define C_DIM 384
#define T_R   16                       // rows per warp chunk
#define WARPS_PER_BLOCK 4
#define THREADS (WARPS_PER_BLOCK * 32)

__device__ __forceinline__ float4 ldg4(const float* p) {
    return *reinterpret_cast<const float4*>(p);
}
__device__ __forceinline__ void stg4(float* p, float4 v) {
    *reinterpret_cast<float4*>(p) = v;
}

// Route components from prev/cur/next given residue flags of this float4's base
// channel: mk = base_channel % 3.  Component j has residue (mk + j) % 3;
// residue 0 -> cur, 1 -> prev (reads t-1), 2 -> next (reads t+1).
__device__ __forceinline__ float4 route(float4 p, float4 c, float4 n,
                                        bool is1, bool is2) {
    float4 o;
    o.x = is1 ? p.x : (is2 ? n.x : c.x);   // residue mk
    o.y = is1 ? n.y : (is2 ? c.y : p.y);   // residue mk+1
    o.z = is1 ? c.z : (is2 ? p.z : n.z);   // residue mk+2
    o.w = is1 ? p.w : (is2 ? n.w : c.w);   // residue mk (again)
    return o;
}

__global__ __launch_bounds__(THREADS)
void ShiftLayer_66932770341347_kernel(const float* __restrict__ in,
                                      float* __restrict__ out) {
    const int warp = blockIdx.x * WARPS_PER_BLOCK + (threadIdx.x >> 5);
    const int lane = threadIdx.x & 31;

    const int chunks_per_b = L_DIM / T_R;                  // 512
    const int b  = warp / chunks_per_b;
    const int t0 = (warp % chunks_per_b) * T_R;

    const size_t row0 = ((size_t)b * L_DIM + t0) * C_DIM + 4 * lane;
    const float* base  = in  + row0;
    float*       obase = out + row0;

    // Residues of the three float4 base channels: (4*lane + 128k) % 3 = (lane + 2k) % 3
    const int m0 = lane % 3;
    const int m1 = (lane + 2) % 3;
    const int m2 = (lane + 1) % 3;
    const bool a1 = (m0 == 1), a2 = (m0 == 2);
    const bool b1 = (m1 == 1), b2 = (m1 == 2);
    const bool c1 = (m2 == 1), c2 = (m2 == 2);

    const float4 z = make_float4(0.f, 0.f, 0.f, 0.f);

    float4 P0, P1, P2, C0, C1, C2, N0, N1, N2;

    // Prologue: prev = row t0-1 (zeros at sequence start), cur = row t0.
    if (t0 > 0) {
        const float* pp = base - C_DIM;
        P0 = ldg4(pp); P1 = ldg4(pp + 128); P2 = ldg4(pp + 256);
    } else {
        P0 = z; P1 = z; P2 = z;
    }
    C0 = ldg4(base); C1 = ldg4(base + 128); C2 = ldg4(base + 256);

    // Main loop: rows t0 .. t0+T_R-2 always have a valid next row.
    #pragma unroll 3
    for (int r = 0; r < T_R - 1; ++r) {
        const float* np = base + (size_t)(r + 1) * C_DIM;
        N0 = ldg4(np); N1 = ldg4(np + 128); N2 = ldg4(np + 256);

        float* op = obase + (size_t)r * C_DIM;
        stg4(op,       route(P0, C0, N0, a1, a2));
        stg4(op + 128, route(P1, C1, N1, b1, b2));
        stg4(op + 256, route(P2, C2, N2, c1, c2));

        P0 = C0; P1 = C1; P2 = C2;
        C0 = N0; C1 = N1; C2 = N2;
    }

    // Last row of the chunk: next row may be past the end of the sequence.
    if (t0 + T_R < L_DIM) {
        const float* np = base + (size_t)T_R * C_DIM;
        N0 = ldg4(np); N1 = ldg4(np + 128); N2 = ldg4(np + 256);
    } else {
        N0 = z; N1 = z; N2 = z;
    }
    {
        float* op = obase + (size_t)(T_R - 1) * C_DIM;
        stg4(op,       route(P0, C0, N0, a1, a2));
        stg4(op + 128, route(P1, C1, N1, b1, b2));
        stg4(op + 256, route(P2, C2, N2, c1, c2));
    }
}

extern "C" void kernel_launch(void* const* d_in, const int* in_sizes, int n_in,
                              void* d_out, int out_size) {
    const float* mem = (const float*)d_in[0];
    float* out = (float*)d_out;
    (void)in_sizes; (void)n_in; (void)out_size;

    const int total_warps = B_DIM * (L_DIM / T_R);         // 4096
    const int grid = total_warps / WARPS_PER_BLOCK;        // 1024 blocks
    ShiftLayer_66932770341347_kernel<<<grid, THREADS>>>(mem, out);
}